// round 2
// baseline (speedup 1.0000x reference)
#include <cuda_runtime.h>

// B=8, L=512, K=512, M=N=P=D=64
#define BB 8
#define LL 512
#define KS 512

typedef unsigned long long u64;

__device__ float g_vkc[BB * KS * 64];   // [b][k][n]
__device__ float g_tmp[BB * LL * 64];   // [b][l][n]

__device__ __forceinline__ void ffma2(u64& d, u64 a, u64 b) {
    asm("fma.rn.f32x2 %0, %1, %2, %0;" : "+l"(d) : "l"(a), "l"(b));
}
__device__ __forceinline__ u64 pack2(float lo, float hi) {
    u64 r;
    asm("mov.b64 %0, {%1, %2};" : "=l"(r) : "f"(lo), "f"(hi));
    return r;
}
__device__ __forceinline__ float hsum2(u64 a) {
    float lo, hi;
    asm("mov.b64 {%0, %1}, %2;" : "=f"(lo), "=f"(hi) : "l"(a));
    return lo + hi;
}

// ---------------------------------------------------------------------------
// Kernel 1: vkc[b,k,n] = sum_p vk[b,k,p,n] * vexp[b,k,p]  (streams vk, 67MB)
//   vectorized: one thread per (bk, n-group-of-4), LDG.128 only
// ---------------------------------------------------------------------------
__global__ __launch_bounds__(256)
void vkc_kernel(const float* __restrict__ vk,
                const float* __restrict__ vexp) {
    __shared__ float se[16 * 64];               // vexp for this block's 16 bk's
    const int tid = threadIdx.x;
    const int bk0 = blockIdx.x * 16;
#pragma unroll
    for (int j = 0; j < 4; ++j)
        se[tid + 256 * j] = vexp[(size_t)bk0 * 64 + tid + 256 * j];
    __syncthreads();

    const int t  = blockIdx.x * 256 + tid;      // 0 .. 65535
    const int n4 = t & 15;
    const int bk = t >> 4;
    const float4* vkp = (const float4*)(vk + (size_t)bk * 4096) + n4;
    const float* ve = se + (tid >> 4) * 64;

    float4 acc = make_float4(0.f, 0.f, 0.f, 0.f);
#pragma unroll 8
    for (int p = 0; p < 64; ++p) {
        float4 v = vkp[p * 16];
        float e  = ve[p];
        acc.x = fmaf(v.x, e, acc.x);
        acc.y = fmaf(v.y, e, acc.y);
        acc.z = fmaf(v.z, e, acc.z);
        acc.w = fmaf(v.w, e, acc.w);
    }
    ((float4*)g_vkc)[t] = acc;
}

// ---------------------------------------------------------------------------
// Kernel 2: per (b, 16 l-rows): scores -> softmax -> tmp = W @ vkc
//   FFMA2 (fma.rn.f32x2) packed along the reduction dims.
//   smem floats: kst[256*66] | S[16*512] | qT2[32*32] | srow[16]
// ---------------------------------------------------------------------------
#define KPITCH 66
#define S_OFF   (256 * KPITCH)                  // 16896
#define QT_OFF  (S_OFF + 8192)                  // 25088
#define SR_OFF  (QT_OFF + 1024)                 // 26112
#define K2_SMEM_BYTES ((SR_OFF + 16) * 4)       // 104512

__global__ __launch_bounds__(256, 2)
void attn_kernel(const float* __restrict__ q,
                 const float* __restrict__ k,
                 const float* __restrict__ scale_p) {
    extern __shared__ float sm[];
    float* kst  = sm;
    float* S    = sm + S_OFF;
    float* qT2  = sm + QT_OFF;                  // [d2][l*2 + parity]
    float* srow = sm + SR_OFF;

    const int tid = threadIdx.x;
    const int b   = blockIdx.x >> 5;
    const int l0  = (blockIdx.x & 31) << 4;
    const float* qb = q + ((size_t)b * LL + l0) * 64;
    const float* kb = k + (size_t)b * KS * 64;
    const float sc  = scale_p[0];

    // stage q tile as d-pairs: qT2[(d>>1)*32 + l*2 + (d&1)]
#pragma unroll
    for (int j = 0; j < 4; ++j) {
        int f = tid + 256 * j;                  // f = l*64 + d
        int l = f >> 6, d = f & 63;
        qT2[(d >> 1) * 32 + l * 2 + (d & 1)] = qb[f];
    }

    const int l_t  = tid & 3;                   // 4 l's
    const int kc_t = tid >> 2;                  // 4 kc's within 256-chunk

    // ---- scores ----
    for (int c = 0; c < 2; ++c) {
        const float* kcb = kb + (size_t)c * 256 * 64;
#pragma unroll 4
        for (int j = 0; j < 64; ++j) {
            int f = tid + 256 * j;              // f = kc*64 + d (coalesced)
            kst[(f >> 6) * KPITCH + (f & 63)] = kcb[f];
        }
        __syncthreads();

        u64 acc[4][4];                          // [j=kc][i=l], packed (even-d, odd-d)
#pragma unroll
        for (int j = 0; j < 4; ++j)
#pragma unroll
            for (int i = 0; i < 4; ++i) acc[j][i] = 0ull;

        const float* kr = kst + (4 * kc_t) * KPITCH;
#pragma unroll 4
        for (int d2 = 0; d2 < 32; ++d2) {
            const u64* qp = (const u64*)(qT2 + d2 * 32 + 8 * l_t);
            u64 q0 = qp[0], q1 = qp[1], q2 = qp[2], q3 = qp[3];
            u64 k0 = *(const u64*)(kr + 2 * d2);
            u64 k1 = *(const u64*)(kr + KPITCH + 2 * d2);
            u64 k2 = *(const u64*)(kr + 2 * KPITCH + 2 * d2);
            u64 k3 = *(const u64*)(kr + 3 * KPITCH + 2 * d2);
            ffma2(acc[0][0], k0, q0); ffma2(acc[0][1], k0, q1);
            ffma2(acc[0][2], k0, q2); ffma2(acc[0][3], k0, q3);
            ffma2(acc[1][0], k1, q0); ffma2(acc[1][1], k1, q1);
            ffma2(acc[1][2], k1, q2); ffma2(acc[1][3], k1, q3);
            ffma2(acc[2][0], k2, q0); ffma2(acc[2][1], k2, q1);
            ffma2(acc[2][2], k2, q2); ffma2(acc[2][3], k2, q3);
            ffma2(acc[3][0], k3, q0); ffma2(acc[3][1], k3, q1);
            ffma2(acc[3][2], k3, q2); ffma2(acc[3][3], k3, q3);
        }
#pragma unroll
        for (int i = 0; i < 4; ++i) {
            float4 v = make_float4(hsum2(acc[0][i]) * sc, hsum2(acc[1][i]) * sc,
                                   hsum2(acc[2][i]) * sc, hsum2(acc[3][i]) * sc);
            *(float4*)(S + (size_t)(4 * l_t + i) * 512 + c * 256 + 4 * kc_t) = v;
        }
        __syncthreads();
    }

    // ---- softmax (unnormalized; 1/sum stashed) ----
    {
        const int w = tid >> 5, lane = tid & 31;
#pragma unroll
        for (int r = 0; r < 2; ++r) {
            int l = w * 2 + r;
            float* Sr = S + (size_t)l * 512;
            float m = -1e30f;
#pragma unroll
            for (int i = 0; i < 16; ++i) m = fmaxf(m, Sr[lane + 32 * i]);
#pragma unroll
            for (int o = 16; o > 0; o >>= 1)
                m = fmaxf(m, __shfl_xor_sync(0xffffffffu, m, o));
            float s = 0.f;
#pragma unroll
            for (int i = 0; i < 16; ++i) {
                float e = __expf(Sr[lane + 32 * i] - m);
                Sr[lane + 32 * i] = e;
                s += e;
            }
#pragma unroll
            for (int o = 16; o > 0; o >>= 1)
                s += __shfl_xor_sync(0xffffffffu, s, o);
            if (lane == 0) srow[l] = 1.f / s;
        }
    }
    __syncthreads();

    // ---- tmp[l][n] = sum_kc W[l][kc] * vkc[b][kc][n], packed along kc ----
    const int l2 = tid >> 5;
    const int n2 = (tid & 31) * 2;
    u64 a00 = 0ull, a01 = 0ull, a10 = 0ull, a11 = 0ull;
    const float* W0 = S + (size_t)(2 * l2) * 512;
    const float* W1 = W0 + 512;
    const float* gv = g_vkc + (size_t)b * KS * 64;

    for (int c = 0; c < 2; ++c) {
#pragma unroll 4
        for (int j = 0; j < 16; ++j) {          // 256x64 floats
            int f4 = tid + 256 * j;
            ((float4*)kst)[f4] = ((const float4*)(gv + (size_t)c * 16384))[f4];
        }
        __syncthreads();
        const float* Wc0 = W0 + c * 256;
        const float* Wc1 = W1 + c * 256;
#pragma unroll 4
        for (int kk = 0; kk < 256; kk += 2) {
            u64 w0p = *(const u64*)(Wc0 + kk);
            u64 w1p = *(const u64*)(Wc1 + kk);
            float2 v0 = *(const float2*)(kst + kk * 64 + n2);
            float2 v1 = *(const float2*)(kst + (kk + 1) * 64 + n2);
            u64 A = pack2(v0.x, v1.x);
            u64 B = pack2(v0.y, v1.y);
            ffma2(a00, w0p, A); ffma2(a01, w0p, B);
            ffma2(a10, w1p, A); ffma2(a11, w1p, B);
        }
        __syncthreads();
    }
    float i0 = srow[2 * l2], i1 = srow[2 * l2 + 1];
    float* tp = g_tmp + ((size_t)b * LL + l0) * 64;
    *(float2*)(tp + (size_t)(2 * l2) * 64 + n2) =
        make_float2(hsum2(a00) * i0, hsum2(a01) * i0);
    *(float2*)(tp + (size_t)(2 * l2 + 1) * 64 + n2) =
        make_float2(hsum2(a10) * i1, hsum2(a11) * i1);
}

// ---------------------------------------------------------------------------
// Kernel 3: per (b,l): attn = vq @ tmp; out = LayerNorm(q + attn)
//   direct coalesced float4 LDG, matvec spread over all 256 threads
// ---------------------------------------------------------------------------
__global__ __launch_bounds__(256)
void out_kernel(const float* __restrict__ q,
                const float* __restrict__ vq,
                const float* __restrict__ gamma,
                const float* __restrict__ beta,
                float* __restrict__ out) {
    __shared__ float stmp[64];
    __shared__ float sq[64];
    __shared__ float sy[64];
    __shared__ float red[4];

    const int tid = threadIdx.x;
    const int bl  = blockIdx.x;                 // b*512 + l
    if (tid < 64) {
        stmp[tid] = g_tmp[(size_t)bl * 64 + tid];
        sq[tid]   = q[(size_t)bl * 64 + tid];
    }
    __syncthreads();

    const int m    = tid >> 2;
    const int part = tid & 3;
    const float4* vr = (const float4*)(vq + (size_t)bl * 4096 + m * 64) + part * 4;
    float acc = 0.f;
#pragma unroll
    for (int i = 0; i < 4; ++i) {
        float4 v = vr[i];
        const float* tp = stmp + part * 16 + i * 4;
        acc = fmaf(v.x, tp[0],
              fmaf(v.y, tp[1],
              fmaf(v.z, tp[2],
              fmaf(v.w, tp[3], acc))));
    }
    acc += __shfl_xor_sync(0xffffffffu, acc, 1);
    acc += __shfl_xor_sync(0xffffffffu, acc, 2);
    if (part == 0) sy[m] = sq[m] + acc;
    __syncthreads();

    float y = 0.f;
    if (tid < 64) {
        y = sy[tid];
        float s1 = y;
#pragma unroll
        for (int o = 16; o > 0; o >>= 1)
            s1 += __shfl_xor_sync(0xffffffffu, s1, o);
        if ((tid & 31) == 0) red[tid >> 5] = s1;
    }
    __syncthreads();
    float mu = (red[0] + red[1]) * (1.f / 64.f);
    if (tid < 64) {
        float d = y - mu;
        float s2 = d * d;
#pragma unroll
        for (int o = 16; o > 0; o >>= 1)
            s2 += __shfl_xor_sync(0xffffffffu, s2, o);
        if ((tid & 31) == 0) red[2 + (tid >> 5)] = s2;
    }
    __syncthreads();
    if (tid < 64) {
        float var = (red[2] + red[3]) * (1.f / 64.f);
        float r = rsqrtf(var + 1e-3f);
        out[(size_t)bl * 64 + tid] =
            (y - mu) * r * __ldg(gamma + tid) + __ldg(beta + tid);
    }
}

// ---------------------------------------------------------------------------
extern "C" void kernel_launch(void* const* d_in, const int* in_sizes, int n_in,
                              void* d_out, int out_size) {
    (void)in_sizes; (void)n_in; (void)out_size;
    const float* q     = (const float*)d_in[0];
    const float* k     = (const float*)d_in[1];
    const float* vq    = (const float*)d_in[2];
    const float* vk    = (const float*)d_in[3];
    const float* vexp  = (const float*)d_in[4];
    const float* scale = (const float*)d_in[5];
    const float* gamma = (const float*)d_in[6];
    const float* beta  = (const float*)d_in[7];
    float* out = (float*)d_out;

    cudaFuncSetAttribute(attn_kernel,
                         cudaFuncAttributeMaxDynamicSharedMemorySize,
                         K2_SMEM_BYTES);

    vkc_kernel<<<BB * KS / 16, 256>>>(vk, vexp);
    attn_kernel<<<BB * (LL / 16), 256, K2_SMEM_BYTES>>>(q, k, scale);
    out_kernel<<<BB * LL, 256>>>(q, vq, gamma, beta, out);
}

// round 5
// speedup vs baseline: 1.2833x; 1.2833x over previous
#include <cuda_runtime.h>

// B=8, L=512, K=512, M=N=P=D=64
#define BB 8
#define LL 512
#define KS 512

typedef unsigned long long u64;

__device__ float g_vkc[BB * KS * 64];   // [b][k][n]
__device__ float g_tmp[BB * LL * 64];   // [b][l][n]

__device__ __forceinline__ void ffma2(u64& d, u64 a, u64 b) {
    asm("fma.rn.f32x2 %0, %1, %2, %0;" : "+l"(d) : "l"(a), "l"(b));
}
__device__ __forceinline__ u64 pack2(float lo, float hi) {
    u64 r;
    asm("mov.b64 %0, {%1, %2};" : "=l"(r) : "f"(lo), "f"(hi));
    return r;
}
__device__ __forceinline__ void unpack2(u64 a, float& lo, float& hi) {
    asm("mov.b64 {%0, %1}, %2;" : "=f"(lo), "=f"(hi) : "l"(a));
}
__device__ __forceinline__ float hsum2(u64 a) {
    float lo, hi; unpack2(a, lo, hi);
    return lo + hi;
}

// ---------------------------------------------------------------------------
// Kernel 1: vkc[b,k,n] = sum_p vk[b,k,p,n]*vexp[b,k,p]   (streams vk, 67MB)
//   2-way p-split: 131072 threads, each sums 32 p's; shfl-combine.
// ---------------------------------------------------------------------------
__global__ __launch_bounds__(256)
void vkc_kernel(const float* __restrict__ vk,
                const float* __restrict__ vexp) {
    __shared__ float se[8 * 64];                 // vexp for the block's 8 bk's
    const int tid = threadIdx.x;
    const int bk0 = blockIdx.x * 8;
    se[tid]       = vexp[(size_t)bk0 * 64 + tid];
    se[tid + 256] = vexp[(size_t)bk0 * 64 + tid + 256];
    __syncthreads();

    const int t  = blockIdx.x * 256 + tid;       // 0 .. 131071
    const int n4 = t & 15;
    const int ph = (t >> 4) & 1;
    const int bk = t >> 5;
    const float4* vkp = (const float4*)(vk + (size_t)bk * 4096 + ph * 2048) + n4;
    const float* ve = se + (tid >> 5) * 64 + ph * 32;

    float4 acc = make_float4(0.f, 0.f, 0.f, 0.f);
#pragma unroll 8
    for (int p = 0; p < 32; ++p) {
        float4 v = vkp[p * 16];
        float e  = ve[p];
        acc.x = fmaf(v.x, e, acc.x);
        acc.y = fmaf(v.y, e, acc.y);
        acc.z = fmaf(v.z, e, acc.z);
        acc.w = fmaf(v.w, e, acc.w);
    }
    acc.x += __shfl_xor_sync(0xffffffffu, acc.x, 16);
    acc.y += __shfl_xor_sync(0xffffffffu, acc.y, 16);
    acc.z += __shfl_xor_sync(0xffffffffu, acc.z, 16);
    acc.w += __shfl_xor_sync(0xffffffffu, acc.w, 16);
    if (ph == 0)
        ((float4*)g_vkc)[(size_t)bk * 16 + n4] = acc;
}

// ---------------------------------------------------------------------------
// Kernel 2: per (b, 32 l-rows), 512 threads, full K resident.
//   smem (words): kst[512*65]=33280 | S[32*516]=16512 | qT2[64*17 u64]=2176 | srow[32]
//   vkc chunk reuses kst region; partial tmp sums reuse S region.
// ---------------------------------------------------------------------------
#define KP    65
#define SP    516
#define KST_W 33280
#define S_W   (KST_W)                       // S base word = 33280
#define S_SZ  (32 * SP)                     // 16512
#define QT_W  (S_W + S_SZ)                  // 49792
#define SR_W  (QT_W + 64 * 34)              // 51968
#define K2_WORDS (SR_W + 32)                // 52000
#define K2_SMEM_BYTES (K2_WORDS * 4)        // 208000

__global__ __launch_bounds__(512, 1)
void attn_kernel(const float* __restrict__ q,
                 const float* __restrict__ k,
                 const float* __restrict__ scale_p) {
    extern __shared__ float sm[];
    float* kst  = sm;                       // k tile [512 kc][KP] / later vkc [512][64]
    float* S    = sm + S_W;                 // weights [32 l][SP] / later partials
    u64*   qt2  = (u64*)(sm + QT_W);        // [d][17]: l-pair packed q
    float* srow = sm + SR_W;

    const int tid  = threadIdx.x;
    const int w    = tid >> 5;
    const int lane = tid & 31;
    const int b    = blockIdx.x >> 4;
    const int l0   = (blockIdx.x & 15) << 5;
    const float* qb = q + ((size_t)b * LL + l0) * 64;
    const float* kb = k + (size_t)b * KS * 64;
    const float sc  = scale_p[0];

    // ---- stage q as l-pairs: qt2[d*17 + lp] = (q[2lp][d], q[2lp+1][d]) ----
#pragma unroll
    for (int it = 0; it < 2; ++it) {
        int d  = tid & 63;
        int lp = (tid >> 6) + 8 * it;       // 0..15
        qt2[d * 17 + lp] = pack2(qb[(2 * lp) * 64 + d], qb[(2 * lp + 1) * 64 + d]);
    }

    // ---- stage k: kst[kc][d], pitch 65  (512*64 floats = 8192 float4) ----
#pragma unroll 4
    for (int it = 0; it < 16; ++it) {       // FIXED: was 64 (OOB read + smem smash)
        int f4 = it * 512 + tid;            // f4 = kc*16 + d4, 0..8191
        float4 v = ((const float4*)kb)[f4];
        int kc = f4 >> 4, d4 = (f4 & 15) * 4;
        float* dst = kst + kc * KP + d4;
        dst[0] = v.x; dst[1] = v.y; dst[2] = v.z; dst[3] = v.w;
    }
    __syncthreads();

    // ---- scores: tile 4kc x 8l, FFMA2 packed over l-pairs ----
    {
        const int lg  = tid & 3;            // l group: 8 l's at 8*lg
        const int kcg = tid >> 2;           // 0..127 -> 4 kc's at 4*kcg
        const float* kr = kst + kcg * 4 * KP;
        const u64*  qp  = qt2;

        u64 acc[4][4];                      // [kc j][l-pair pp]
#pragma unroll
        for (int j = 0; j < 4; ++j)
#pragma unroll
            for (int p = 0; p < 4; ++p) acc[j][p] = 0ull;

#pragma unroll 4
        for (int d = 0; d < 64; ++d) {
            u64 K0 = pack2(kr[d], kr[d]);
            u64 K1 = pack2(kr[KP + d], kr[KP + d]);
            u64 K2 = pack2(kr[2 * KP + d], kr[2 * KP + d]);
            u64 K3 = pack2(kr[3 * KP + d], kr[3 * KP + d]);
            const u64* qd = qp + d * 17 + 4 * lg;
            u64 q0 = qd[0], q1 = qd[1], q2 = qd[2], q3 = qd[3];
            ffma2(acc[0][0], K0, q0); ffma2(acc[0][1], K0, q1);
            ffma2(acc[0][2], K0, q2); ffma2(acc[0][3], K0, q3);
            ffma2(acc[1][0], K1, q0); ffma2(acc[1][1], K1, q1);
            ffma2(acc[1][2], K1, q2); ffma2(acc[1][3], K1, q3);
            ffma2(acc[2][0], K2, q0); ffma2(acc[2][1], K2, q1);
            ffma2(acc[2][2], K2, q2); ffma2(acc[2][3], K2, q3);
            ffma2(acc[3][0], K3, q0); ffma2(acc[3][1], K3, q1);
            ffma2(acc[3][2], K3, q2); ffma2(acc[3][3], K3, q3);
        }
        // scaled store: S[l][kc]
#pragma unroll
        for (int j = 0; j < 4; ++j)
#pragma unroll
            for (int p = 0; p < 4; ++p) {
                float lo, hi; unpack2(acc[j][p], lo, hi);
                int l  = 8 * lg + 2 * p;
                int kc = 4 * kcg + j;
                S[l * SP + kc]       = lo * sc;
                S[(l + 1) * SP + kc] = hi * sc;
            }
    }
    __syncthreads();

    // ---- softmax (unnormalized, 1/sum stashed): 16 warps x 2 rows ----
#pragma unroll
    for (int r = 0; r < 2; ++r) {
        int l = w * 2 + r;
        float* Sr = S + l * SP;
        float m = -1e30f;
#pragma unroll
        for (int i = 0; i < 16; ++i) m = fmaxf(m, Sr[lane + 32 * i]);
#pragma unroll
        for (int o = 16; o > 0; o >>= 1)
            m = fmaxf(m, __shfl_xor_sync(0xffffffffu, m, o));
        float s = 0.f;
#pragma unroll
        for (int i = 0; i < 16; ++i) {
            float e = __expf(Sr[lane + 32 * i] - m);
            Sr[lane + 32 * i] = e;
            s += e;
        }
#pragma unroll
        for (int o = 16; o > 0; o >>= 1)
            s += __shfl_xor_sync(0xffffffffu, s, o);
        if (lane == 0) srow[l] = 1.f / s;
    }
    __syncthreads();

    // ---- stage vkc into kst region: [512 kc][64 n] ----
    {
        const float4* gv4 = (const float4*)(g_vkc + (size_t)b * KS * 64);
#pragma unroll 4
        for (int it = 0; it < 16; ++it)
            ((float4*)kst)[it * 512 + tid] = gv4[it * 512 + tid];
    }
    __syncthreads();

    // ---- tmp: 4-way kc split, tile 8l x 2n, FFMA2 packed over kc-pairs ----
    const int kcs = w & 3;                  // kc range [128*kcs, +128)
    const int wq  = w >> 2;                 // l octet: 8*wq .. 8*wq+7
    u64 acc[8][2];                          // [l j][n in {2*lane, 2*lane+1}]
#pragma unroll
    for (int j = 0; j < 8; ++j) { acc[j][0] = 0ull; acc[j][1] = 0ull; }

    {
        const float* vb = kst + 2 * lane;
        const float* Wb = S + (8 * wq) * SP;
#pragma unroll 2
        for (int kk = 0; kk < 32; ++kk) {
            int kc = 128 * kcs + 4 * kk;
            const float* vr = vb + kc * 64;
            float2 va = *(const float2*)(vr);
            float2 vb2 = *(const float2*)(vr + 64);
            float2 vc = *(const float2*)(vr + 128);
            float2 vd = *(const float2*)(vr + 192);
            u64 A0 = pack2(va.x, vb2.x), A1 = pack2(va.y, vb2.y);   // kc,kc+1
            u64 B0 = pack2(vc.x, vd.x),  B1 = pack2(vc.y, vd.y);    // kc+2,kc+3
#pragma unroll
            for (int j = 0; j < 8; ++j) {
                float4 wv = *(const float4*)(Wb + j * SP + kc);     // aligned broadcast
                u64 w01 = pack2(wv.x, wv.y);
                u64 w23 = pack2(wv.z, wv.w);
                ffma2(acc[j][0], w01, A0); ffma2(acc[j][1], w01, A1);
                ffma2(acc[j][0], w23, B0); ffma2(acc[j][1], w23, B1);
            }
        }
    }
    __syncthreads();                        // all W reads done; reuse S for partials

    // partials: P[kcs][l][n] in S region
    {
        float* P = S + kcs * 2048;
#pragma unroll
        for (int j = 0; j < 8; ++j) {
            int l = 8 * wq + j;
            *(float2*)(P + l * 64 + 2 * lane) =
                make_float2(hsum2(acc[j][0]), hsum2(acc[j][1]));
        }
    }
    __syncthreads();

    // reduce 4 partials, normalize, store
    {
        int idx = tid * 4;                  // (l,n0): l = idx>>6
        int l   = idx >> 6;
        float4 s0 = *(const float4*)(S + idx);
        float4 s1 = *(const float4*)(S + 2048 + idx);
        float4 s2 = *(const float4*)(S + 4096 + idx);
        float4 s3 = *(const float4*)(S + 6144 + idx);
        float inv = srow[l];
        float4 o;
        o.x = (s0.x + s1.x + s2.x + s3.x) * inv;
        o.y = (s0.y + s1.y + s2.y + s3.y) * inv;
        o.z = (s0.z + s1.z + s2.z + s3.z) * inv;
        o.w = (s0.w + s1.w + s2.w + s3.w) * inv;
        *(float4*)(g_tmp + ((size_t)b * LL + l0) * 64 + idx) = o;
    }
}

// ---------------------------------------------------------------------------
// Kernel 3: per (b,l): attn = vq @ tmp; out = LayerNorm(q + attn)  (streams vq)
// ---------------------------------------------------------------------------
__global__ __launch_bounds__(256)
void out_kernel(const float* __restrict__ q,
                const float* __restrict__ vq,
                const float* __restrict__ gamma,
                const float* __restrict__ beta,
                float* __restrict__ out) {
    __shared__ float stmp[64];
    __shared__ float sq[64];
    __shared__ float sy[64];
    __shared__ float red[4];

    const int tid = threadIdx.x;
    const int bl  = blockIdx.x;             // b*512 + l
    if (tid < 64) {
        stmp[tid] = g_tmp[(size_t)bl * 64 + tid];
        sq[tid]   = q[(size_t)bl * 64 + tid];
    }
    __syncthreads();

    const int m    = tid >> 2;
    const int part = tid & 3;
    const float4* vr = (const float4*)(vq + (size_t)bl * 4096 + m * 64) + part * 4;
    float acc = 0.f;
#pragma unroll
    for (int i = 0; i < 4; ++i) {
        float4 v = vr[i];
        const float* tp = stmp + part * 16 + i * 4;
        acc = fmaf(v.x, tp[0],
              fmaf(v.y, tp[1],
              fmaf(v.z, tp[2],
              fmaf(v.w, tp[3], acc))));
    }
    acc += __shfl_xor_sync(0xffffffffu, acc, 1);
    acc += __shfl_xor_sync(0xffffffffu, acc, 2);
    if (part == 0) sy[m] = sq[m] + acc;
    __syncthreads();

    float y = 0.f;
    if (tid < 64) {
        y = sy[tid];
        float s1 = y;
#pragma unroll
        for (int o = 16; o > 0; o >>= 1)
            s1 += __shfl_xor_sync(0xffffffffu, s1, o);
        if ((tid & 31) == 0) red[tid >> 5] = s1;
    }
    __syncthreads();
    float mu = (red[0] + red[1]) * (1.f / 64.f);
    if (tid < 64) {
        float d = y - mu;
        float s2 = d * d;
#pragma unroll
        for (int o = 16; o > 0; o >>= 1)
            s2 += __shfl_xor_sync(0xffffffffu, s2, o);
        if ((tid & 31) == 0) red[2 + (tid >> 5)] = s2;
    }
    __syncthreads();
    if (tid < 64) {
        float var = (red[2] + red[3]) * (1.f / 64.f);
        float r = rsqrtf(var + 1e-3f);
        out[(size_t)bl * 64 + tid] =
            (y - mu) * r * __ldg(gamma + tid) + __ldg(beta + tid);
    }
}

// ---------------------------------------------------------------------------
extern "C" void kernel_launch(void* const* d_in, const int* in_sizes, int n_in,
                              void* d_out, int out_size) {
    (void)in_sizes; (void)n_in; (void)out_size;
    const float* q     = (const float*)d_in[0];
    const float* k     = (const float*)d_in[1];
    const float* vq    = (const float*)d_in[2];
    const float* vk    = (const float*)d_in[3];
    const float* vexp  = (const float*)d_in[4];
    const float* scale = (const float*)d_in[5];
    const float* gamma = (const float*)d_in[6];
    const float* beta  = (const float*)d_in[7];
    float* out = (float*)d_out;

    cudaFuncSetAttribute(attn_kernel,
                         cudaFuncAttributeMaxDynamicSharedMemorySize,
                         K2_SMEM_BYTES);

    vkc_kernel<<<BB * KS / 8, 256>>>(vk, vexp);
    attn_kernel<<<BB * (LL / 32), 512, K2_SMEM_BYTES>>>(q, k, scale);
    out_kernel<<<BB * LL, 256>>>(q, vq, gamma, beta, out);
}

// round 6
// speedup vs baseline: 1.3305x; 1.0367x over previous
#include <cuda_runtime.h>

// B=8, L=512, K=512, M=N=P=D=64
#define BB 8
#define LL 512
#define KS 512

typedef unsigned long long u64;

__device__ float g_vkc[BB * KS * 64];     // [b][k][n]
__device__ float g_S[BB * LL * KS];       // raw scaled scores [b][l][kc]
__device__ float g_tmp[BB * LL * 64];     // [b][l][n]

__device__ __forceinline__ void ffma2(u64& d, u64 a, u64 b) {
    asm("fma.rn.f32x2 %0, %1, %2, %0;" : "+l"(d) : "l"(a), "l"(b));
}
__device__ __forceinline__ u64 pack2(float lo, float hi) {
    u64 r;
    asm("mov.b64 %0, {%1, %2};" : "=l"(r) : "f"(lo), "f"(hi));
    return r;
}
__device__ __forceinline__ void unpack2(u64 a, float& lo, float& hi) {
    asm("mov.b64 {%0, %1}, %2;" : "=f"(lo), "=f"(hi) : "l"(a));
}
__device__ __forceinline__ float hsum2(u64 a) {
    float lo, hi; unpack2(a, lo, hi);
    return lo + hi;
}

// ---------------------------------------------------------------------------
// Kernel 1 (fused, role-split):
//   blocks [0,256):  scores  g_S[b][l][kc] = sc * q[l]·k[kc]   (FMA-bound)
//   blocks [256,768): vkc[b,k,n] = sum_p vk[b,k,p,n]*vexp[b,k,p] (DRAM-bound)
//   Independent inputs -> concurrent execution hides scores under vkc stream.
// scores smem (words): kst[128*65]=8320 | qt2[64*33 u64] at 8320 (4224 words)
// ---------------------------------------------------------------------------
#define SC_KST 0
#define SC_QT  8320
#define K1_SMEM_BYTES ((8320 + 64 * 33 * 2) * 4)   // 50176

__global__ __launch_bounds__(256)
void k1_kernel(const float* __restrict__ vk,
               const float* __restrict__ vexp,
               const float* __restrict__ q,
               const float* __restrict__ k,
               const float* __restrict__ scale_p) {
    extern __shared__ float sm[];
    const int tid = threadIdx.x;

    if (blockIdx.x >= 256) {
        // ---------------- vkc role (proven R5 body) ----------------
        float* se = sm;                          // 512 floats
        const int vb  = blockIdx.x - 256;        // 0..511
        const int bk0 = vb * 8;
        se[tid]       = vexp[(size_t)bk0 * 64 + tid];
        se[tid + 256] = vexp[(size_t)bk0 * 64 + tid + 256];
        __syncthreads();

        const int t  = vb * 256 + tid;           // 0 .. 131071
        const int n4 = t & 15;
        const int ph = (t >> 4) & 1;
        const int bk = t >> 5;
        const float4* vkp = (const float4*)(vk + (size_t)bk * 4096 + ph * 2048) + n4;
        const float* ve = se + (tid >> 5) * 64 + ph * 32;

        float4 acc = make_float4(0.f, 0.f, 0.f, 0.f);
#pragma unroll 8
        for (int p = 0; p < 32; ++p) {
            float4 v = vkp[p * 16];
            float e  = ve[p];
            acc.x = fmaf(v.x, e, acc.x);
            acc.y = fmaf(v.y, e, acc.y);
            acc.z = fmaf(v.z, e, acc.z);
            acc.w = fmaf(v.w, e, acc.w);
        }
        acc.x += __shfl_xor_sync(0xffffffffu, acc.x, 16);
        acc.y += __shfl_xor_sync(0xffffffffu, acc.y, 16);
        acc.z += __shfl_xor_sync(0xffffffffu, acc.z, 16);
        acc.w += __shfl_xor_sync(0xffffffffu, acc.w, 16);
        if (ph == 0)
            ((float4*)g_vkc)[(size_t)bk * 16 + n4] = acc;
        return;
    }

    // ---------------- scores role ----------------
    float* kst = sm + SC_KST;                    // [128 kc][65]
    u64*   qt2 = (u64*)(sm + SC_QT);             // [64 d][33]: l-pair packed q

    const int bid = blockIdx.x;                  // 0..255
    const int b   = bid >> 5;
    const int rem = bid & 31;
    const int l0  = (rem >> 2) * 64;
    const int kc0 = (rem & 3) * 128;
    const float* qb = q + ((size_t)b * LL + l0) * 64;
    const float* kb = k + ((size_t)b * KS + kc0) * 64;
    const float sc  = scale_p[0];

    // stage q transposed into l-pair u64s: qt2[d*33 + (l>>1)], halves by parity
    {
        float* qw = (float*)qt2;
#pragma unroll
        for (int it = 0; it < 16; ++it) {
            int idx = it * 256 + tid;            // l*64 + d, l in 0..63
            float v = qb[idx];
            int l = idx >> 6, d = idx & 63;
            qw[2 * (d * 33 + (l >> 1)) + (l & 1)] = v;
        }
    }
    // stage k tile [128 kc][64 d] at pitch 65
#pragma unroll
    for (int it = 0; it < 8; ++it) {
        int f4 = it * 256 + tid;                 // kc*16 + d4
        float4 v = ((const float4*)kb)[f4];
        int kc = f4 >> 4, d4 = (f4 & 15) * 4;
        float* dst = kst + kc * 65 + d4;
        dst[0] = v.x; dst[1] = v.y; dst[2] = v.z; dst[3] = v.w;
    }
    __syncthreads();

    const int lane = tid & 31;                   // kc = lane + 32*j
    const int lg   = tid >> 5;                   // l octet: 8*lg
    const float* kr = kst + lane * 65;

    u64 acc[4][4];                               // [j kc][p l-pair]
#pragma unroll
    for (int j = 0; j < 4; ++j)
#pragma unroll
        for (int p = 0; p < 4; ++p) acc[j][p] = 0ull;

#pragma unroll 4
    for (int d = 0; d < 64; ++d) {
        float k0 = kr[d];
        float k1 = kr[32 * 65 + d];
        float k2 = kr[64 * 65 + d];
        float k3 = kr[96 * 65 + d];
        u64 K0 = pack2(k0, k0), K1 = pack2(k1, k1);
        u64 K2 = pack2(k2, k2), K3 = pack2(k3, k3);
        const u64* qd = qt2 + d * 33 + 4 * lg;   // warp-broadcast
        u64 q0 = qd[0], q1 = qd[1], q2 = qd[2], q3 = qd[3];
        ffma2(acc[0][0], K0, q0); ffma2(acc[0][1], K0, q1);
        ffma2(acc[0][2], K0, q2); ffma2(acc[0][3], K0, q3);
        ffma2(acc[1][0], K1, q0); ffma2(acc[1][1], K1, q1);
        ffma2(acc[1][2], K1, q2); ffma2(acc[1][3], K1, q3);
        ffma2(acc[2][0], K2, q0); ffma2(acc[2][1], K2, q1);
        ffma2(acc[2][2], K2, q2); ffma2(acc[2][3], K2, q3);
        ffma2(acc[3][0], K3, q0); ffma2(acc[3][1], K3, q1);
        ffma2(acc[3][2], K3, q2); ffma2(acc[3][3], K3, q3);
    }

    // write S (scaled): per (p,j): rows l, l+1, col kc0 + lane + 32*j (coalesced)
#pragma unroll
    for (int p = 0; p < 4; ++p) {
        int l = l0 + 8 * lg + 2 * p;
        float* r0 = g_S + ((size_t)b * LL + l) * KS + kc0 + lane;
        float* r1 = r0 + KS;
#pragma unroll
        for (int j = 0; j < 4; ++j) {
            float lo, hi; unpack2(acc[j][p], lo, hi);
            r0[32 * j] = lo * sc;
            r1[32 * j] = hi * sc;
        }
    }
}

// ---------------------------------------------------------------------------
// Kernel 2: per (b, 32 l-rows), 512 threads: softmax(S) @ vkc -> g_tmp
//   smem (words): kst[512*64]=32768 | S[32*516]=16512 | srow[32]
// ---------------------------------------------------------------------------
#define T_KST 0
#define T_S   32768
#define T_SR  (32768 + 16512)                    // 49280
#define K2_WORDS (T_SR + 32)                     // 49312
#define K2_SMEM_BYTES (K2_WORDS * 4)             // 197248
#define SP 516

__global__ __launch_bounds__(512, 1)
void k2_kernel() {
    extern __shared__ float sm[];
    float* kst  = sm + T_KST;                    // vkc [512 kc][64 n]
    float* S    = sm + T_S;                      // [32 l][SP] weights / partials
    float* srow = sm + T_SR;

    const int tid  = threadIdx.x;
    const int w    = tid >> 5;
    const int lane = tid & 31;
    const int b    = blockIdx.x >> 4;
    const int l0   = (blockIdx.x & 15) << 5;

    // ---- load raw scores: 32 x 512 ----
    {
        const float4* gs4 = (const float4*)(g_S + ((size_t)b * LL + l0) * KS);
#pragma unroll
        for (int it = 0; it < 8; ++it) {
            int f4 = it * 512 + tid;             // l*128 + kc4
            int l = f4 >> 7, kc4 = f4 & 127;
            *(float4*)(S + l * SP + 4 * kc4) = gs4[f4];
        }
    }
    __syncthreads();

    // ---- softmax (unnormalized, 1/sum stashed): 16 warps x 2 rows ----
#pragma unroll
    for (int r = 0; r < 2; ++r) {
        int l = w * 2 + r;
        float* Sr = S + l * SP;
        float m = -1e30f;
#pragma unroll
        for (int i = 0; i < 16; ++i) m = fmaxf(m, Sr[lane + 32 * i]);
#pragma unroll
        for (int o = 16; o > 0; o >>= 1)
            m = fmaxf(m, __shfl_xor_sync(0xffffffffu, m, o));
        float s = 0.f;
#pragma unroll
        for (int i = 0; i < 16; ++i) {
            float e = __expf(Sr[lane + 32 * i] - m);
            Sr[lane + 32 * i] = e;
            s += e;
        }
#pragma unroll
        for (int o = 16; o > 0; o >>= 1)
            s += __shfl_xor_sync(0xffffffffu, s, o);
        if (lane == 0) srow[l] = 1.f / s;
    }

    // ---- stage vkc [512 kc][64 n] (straight copy) ----
    {
        const float4* gv4 = (const float4*)(g_vkc + (size_t)b * KS * 64);
#pragma unroll 4
        for (int it = 0; it < 16; ++it)
            ((float4*)kst)[it * 512 + tid] = gv4[it * 512 + tid];
    }
    __syncthreads();

    // ---- tmp: 4-way kc split, tile 8l x 2n, FFMA2 packed over kc-pairs ----
    const int kcs = w & 3;
    const int wq  = w >> 2;
    u64 acc[8][2];
#pragma unroll
    for (int j = 0; j < 8; ++j) { acc[j][0] = 0ull; acc[j][1] = 0ull; }

    {
        const float* vb = kst + 2 * lane;
        const float* Wb = S + (8 * wq) * SP;
#pragma unroll 2
        for (int kk = 0; kk < 32; ++kk) {
            int kc = 128 * kcs + 4 * kk;
            const float* vr = vb + kc * 64;
            float2 va = *(const float2*)(vr);
            float2 vb2 = *(const float2*)(vr + 64);
            float2 vc = *(const float2*)(vr + 128);
            float2 vd = *(const float2*)(vr + 192);
            u64 A0 = pack2(va.x, vb2.x), A1 = pack2(va.y, vb2.y);
            u64 B0 = pack2(vc.x, vd.x),  B1 = pack2(vc.y, vd.y);
#pragma unroll
            for (int j = 0; j < 8; ++j) {
                float4 wv = *(const float4*)(Wb + j * SP + kc);   // aligned bcast
                u64 w01 = pack2(wv.x, wv.y);
                u64 w23 = pack2(wv.z, wv.w);
                ffma2(acc[j][0], w01, A0); ffma2(acc[j][1], w01, A1);
                ffma2(acc[j][0], w23, B0); ffma2(acc[j][1], w23, B1);
            }
        }
    }
    __syncthreads();                             // W reads done; reuse S

    {
        float* P = S + kcs * 2048;
#pragma unroll
        for (int j = 0; j < 8; ++j) {
            int l = 8 * wq + j;
            *(float2*)(P + l * 64 + 2 * lane) =
                make_float2(hsum2(acc[j][0]), hsum2(acc[j][1]));
        }
    }
    __syncthreads();

    {
        int idx = tid * 4;
        int l   = idx >> 6;
        float4 s0 = *(const float4*)(S + idx);
        float4 s1 = *(const float4*)(S + 2048 + idx);
        float4 s2 = *(const float4*)(S + 4096 + idx);
        float4 s3 = *(const float4*)(S + 6144 + idx);
        float inv = srow[l];
        float4 o;
        o.x = (s0.x + s1.x + s2.x + s3.x) * inv;
        o.y = (s0.y + s1.y + s2.y + s3.y) * inv;
        o.z = (s0.z + s1.z + s2.z + s3.z) * inv;
        o.w = (s0.w + s1.w + s2.w + s3.w) * inv;
        *(float4*)(g_tmp + ((size_t)b * LL + l0) * 64 + idx) = o;
    }
}

// ---------------------------------------------------------------------------
// Kernel 3: per (b,l): attn = vq @ tmp; out = LayerNorm(q + attn)  (streams vq)
// ---------------------------------------------------------------------------
__global__ __launch_bounds__(256)
void out_kernel(const float* __restrict__ q,
                const float* __restrict__ vq,
                const float* __restrict__ gamma,
                const float* __restrict__ beta,
                float* __restrict__ out) {
    __shared__ float stmp[64];
    __shared__ float sq[64];
    __shared__ float sy[64];
    __shared__ float red[4];

    const int tid = threadIdx.x;
    const int bl  = blockIdx.x;
    if (tid < 64) {
        stmp[tid] = g_tmp[(size_t)bl * 64 + tid];
        sq[tid]   = q[(size_t)bl * 64 + tid];
    }
    __syncthreads();

    const int m    = tid >> 2;
    const int part = tid & 3;
    const float4* vr = (const float4*)(vq + (size_t)bl * 4096 + m * 64) + part * 4;
    float acc = 0.f;
#pragma unroll
    for (int i = 0; i < 4; ++i) {
        float4 v = vr[i];
        const float* tp = stmp + part * 16 + i * 4;
        acc = fmaf(v.x, tp[0],
              fmaf(v.y, tp[1],
              fmaf(v.z, tp[2],
              fmaf(v.w, tp[3], acc))));
    }
    acc += __shfl_xor_sync(0xffffffffu, acc, 1);
    acc += __shfl_xor_sync(0xffffffffu, acc, 2);
    if (part == 0) sy[m] = sq[m] + acc;
    __syncthreads();

    float y = 0.f;
    if (tid < 64) {
        y = sy[tid];
        float s1 = y;
#pragma unroll
        for (int o = 16; o > 0; o >>= 1)
            s1 += __shfl_xor_sync(0xffffffffu, s1, o);
        if ((tid & 31) == 0) red[tid >> 5] = s1;
    }
    __syncthreads();
    float mu = (red[0] + red[1]) * (1.f / 64.f);
    if (tid < 64) {
        float d = y - mu;
        float s2 = d * d;
#pragma unroll
        for (int o = 16; o > 0; o >>= 1)
            s2 += __shfl_xor_sync(0xffffffffu, s2, o);
        if ((tid & 31) == 0) red[2 + (tid >> 5)] = s2;
    }
    __syncthreads();
    if (tid < 64) {
        float var = (red[2] + red[3]) * (1.f / 64.f);
        float r = rsqrtf(var + 1e-3f);
        out[(size_t)bl * 64 + tid] =
            (y - mu) * r * __ldg(gamma + tid) + __ldg(beta + tid);
    }
}

// ---------------------------------------------------------------------------
extern "C" void kernel_launch(void* const* d_in, const int* in_sizes, int n_in,
                              void* d_out, int out_size) {
    (void)in_sizes; (void)n_in; (void)out_size;
    const float* q     = (const float*)d_in[0];
    const float* k     = (const float*)d_in[1];
    const float* vq    = (const float*)d_in[2];
    const float* vk    = (const float*)d_in[3];
    const float* vexp  = (const float*)d_in[4];
    const float* scale = (const float*)d_in[5];
    const float* gamma = (const float*)d_in[6];
    const float* beta  = (const float*)d_in[7];
    float* out = (float*)d_out;

    cudaFuncSetAttribute(k1_kernel,
                         cudaFuncAttributeMaxDynamicSharedMemorySize,
                         K1_SMEM_BYTES);
    cudaFuncSetAttribute(k2_kernel,
                         cudaFuncAttributeMaxDynamicSharedMemorySize,
                         K2_SMEM_BYTES);

    k1_kernel<<<768, 256, K1_SMEM_BYTES>>>(vk, vexp, q, k, scale);
    k2_kernel<<<BB * (LL / 32), 512, K2_SMEM_BYTES>>>();
    out_kernel<<<BB * LL, 256>>>(q, vq, gamma, beta, out);
}